// round 1
// baseline (speedup 1.0000x reference)
#include <cuda_runtime.h>
#include <cstdint>

#define NPTS 100000
#define K3   27
#define CIN  128
#define CH   64
#define MT   256          // points per block
#define NTHR 512          // 16 warps
#define ASTR 132          // A smem row stride (words), 132 % 32 == 4 -> conflict-free frags
#define SMEM_WORDS (MT*ASTR + 8192 + MT*K3)
#define SMEM_BYTES (SMEM_WORDS * 4)

// ---------------- device scratch (static: no allocation allowed) ----------------
__device__ __align__(16) float    g_h[(size_t)NPTS * 128];      // [h0 | h1], 51.2 MB
__device__ __align__(16) unsigned g_W00p[K3 * CIN * CH];        // packed tf32
__device__ __align__(16) unsigned g_Wcatp[K3 * CH * 128];       // [k][cin64][n128] (W01|W11)
__device__ __align__(16) unsigned g_W10p[CIN * CH];
__device__ __align__(16) unsigned g_W12p[CH * CH];

// ---------------- helpers ----------------
__device__ __forceinline__ unsigned f2tf(float f) {
    unsigned u; asm("cvt.rna.tf32.f32 %0, %1;" : "=r"(u) : "f"(f)); return u;
}

// packed B layout: element (cin, n) of a [Kdim, NW] slice goes to
//   (cin>>3)*(NW*8) + n*8 + (cin&3)*2 + ((cin>>2)&1)
// so the two B-frag regs (k = lane%4 and lane%4+4 within an 8-deep K group)
// are adjacent words -> one LDS.64 per (kstep, ntile).
__device__ __forceinline__ int pack_off(int cin, int n, int NW) {
    return ((cin >> 3) * (NW * 8)) + n * 8 + ((cin & 3) << 1) + ((cin >> 2) & 1);
}

__device__ __forceinline__ void mma_tf32(float* d, unsigned a0, unsigned a1,
                                         unsigned a2, unsigned a3,
                                         unsigned b0, unsigned b1) {
    asm volatile(
        "mma.sync.aligned.m16n8k8.row.col.f32.tf32.tf32.f32 "
        "{%0,%1,%2,%3}, {%4,%5,%6,%7}, {%8,%9}, {%0,%1,%2,%3};\n"
        : "+f"(d[0]), "+f"(d[1]), "+f"(d[2]), "+f"(d[3])
        : "r"(a0), "r"(a1), "r"(a2), "r"(a3), "r"(b0), "r"(b1));
}

// ---------------- weight packing (runs every call; deterministic, tiny) ----------------
#define PACK_W00   (K3 * CIN * CH)        // 221184
#define PACK_WCAT  (K3 * CH * 128)        // 221184
#define PACK_TOTAL (PACK_W00 + PACK_WCAT + CIN*CH + CH*CH)

__global__ void pack_weights(const float* __restrict__ W00, const float* __restrict__ W01,
                             const float* __restrict__ W11, const float* __restrict__ W10,
                             const float* __restrict__ W12) {
    int t = blockIdx.x * blockDim.x + threadIdx.x;
    if (t < PACK_W00) {
        int k = t / (CIN*CH); int r = t % (CIN*CH); int c = r / CH; int n = r % CH;
        g_W00p[k*CIN*CH + pack_off(c, n, CH)] = f2tf(W00[t]);
        return;
    }
    t -= PACK_W00;
    if (t < PACK_WCAT) {
        int k = t / (CH*128); int r = t % (CH*128); int c = r / 128; int n = r % 128;
        float v = (n < CH) ? W01[k*CH*CH + c*CH + n] : W11[k*CH*CH + c*CH + (n - CH)];
        g_Wcatp[k*CH*128 + pack_off(c, n, 128)] = f2tf(v);
        return;
    }
    t -= PACK_WCAT;
    if (t < CIN*CH) { int c = t / CH, n = t % CH; g_W10p[pack_off(c, n, CH)] = f2tf(W10[t]); return; }
    t -= CIN*CH;
    if (t < CH*CH)  { int c = t / CH, n = t % CH; g_W12p[pack_off(c, n, CH)] = f2tf(W12[t]); return; }
}

// ---------------- kernel A: h = [ relu(conv0_0(x)) | relu(x @ W10 + b10) ] ----------------
__global__ __launch_bounds__(NTHR, 1)
void convA(const float* __restrict__ x, const int* __restrict__ nbr,
           const float* __restrict__ b00, const float* __restrict__ b10) {
    extern __shared__ unsigned sm[];
    unsigned* As = sm;                    // MT x ASTR
    unsigned* Ws = As + MT * ASTR;        // 8192 words (one packed [128,64] slice)
    int*      nb = (int*)(Ws + CIN * CH); // MT*27

    const int base = blockIdx.x * MT;
    const int tid  = threadIdx.x;
    const int rows = min(MT, NPTS - base);

    for (int i = tid; i < rows * K3; i += NTHR) nb[i] = nbr[(size_t)base * K3 + i];

    float acc0[8][4] = {};   // conv0_0
    float acc1[8][4] = {};   // 1x1 W10
    const int lane = tid & 31, warp = tid >> 5;
    const int row0 = warp * 16;
    const int gr = lane >> 2, gc = lane & 3;
    const int gR = tid >> 1, gH = tid & 1;          // gather: 2 threads per row

    for (int k = 0; k < 28; ++k) {
        __syncthreads();
        // ---- gather A tile (tf32) ----
        {
            int idx;
            if (gR < rows) idx = (k < K3) ? nb[gR * K3 + k] : (base + gR);
            else           idx = NPTS;
            unsigned* dst = As + gR * ASTR + gH * 64;
            if (idx < NPTS) {
                const float4* src = (const float4*)(x + (size_t)idx * CIN + gH * 64);
                #pragma unroll
                for (int j = 0; j < 16; ++j) {
                    float4 v = src[j];
                    uint4 u = { f2tf(v.x), f2tf(v.y), f2tf(v.z), f2tf(v.w) };
                    *(uint4*)(dst + j * 4) = u;
                }
            } else {
                uint4 z = {0u,0u,0u,0u};
                #pragma unroll
                for (int j = 0; j < 16; ++j) *(uint4*)(dst + j * 4) = z;
            }
        }
        // ---- copy packed weight slice (linear, coalesced) ----
        {
            const unsigned* Wg = (k < K3) ? (g_W00p + k * CIN * CH) : g_W10p;
            #pragma unroll
            for (int i2 = 0; i2 < (CIN*CH)/(NTHR*4); ++i2) {
                int i = (i2 * NTHR + tid) * 4;
                *(uint4*)(Ws + i) = *(const uint4*)(Wg + i);
            }
        }
        __syncthreads();
        // ---- MMA: [MT,128] x [128,64] ----
        float (*acc)[4] = (k < K3) ? acc0 : acc1;
        #pragma unroll
        for (int g = 0; g < 16; ++g) {
            const int c = g * 8;
            unsigned a0 = As[(row0+gr  ) * ASTR + c + gc];
            unsigned a1 = As[(row0+gr+8) * ASTR + c + gc];
            unsigned a2 = As[(row0+gr  ) * ASTR + c + gc + 4];
            unsigned a3 = As[(row0+gr+8) * ASTR + c + gc + 4];
            #pragma unroll
            for (int nt = 0; nt < 8; ++nt) {
                uint2 b = *(uint2*)(Ws + g*(CH*8) + (nt*8 + (lane>>2))*8 + (lane&3)*2);
                mma_tf32(acc[nt], a0, a1, a2, a3, b.x, b.y);
            }
        }
    }
    // ---- epilogue: relu + store h ----
    const int p0 = base + row0 + gr, p1 = p0 + 8;
    #pragma unroll
    for (int nt = 0; nt < 8; ++nt) {
        const int col = nt * 8 + (lane & 3) * 2;
        float ba0 = b00[col], ba1 = b00[col+1];
        float bb0 = b10[col], bb1 = b10[col+1];
        if (p0 < NPTS) {
            float2 v0 = { fmaxf(acc0[nt][0] + ba0, 0.f), fmaxf(acc0[nt][1] + ba1, 0.f) };
            *(float2*)(g_h + (size_t)p0*128 + col) = v0;
            float2 v1 = { fmaxf(acc1[nt][0] + bb0, 0.f), fmaxf(acc1[nt][1] + bb1, 0.f) };
            *(float2*)(g_h + (size_t)p0*128 + 64 + col) = v1;
        }
        if (p1 < NPTS) {
            float2 v0 = { fmaxf(acc0[nt][2] + ba0, 0.f), fmaxf(acc0[nt][3] + ba1, 0.f) };
            *(float2*)(g_h + (size_t)p1*128 + col) = v0;
            float2 v1 = { fmaxf(acc1[nt][2] + bb0, 0.f), fmaxf(acc1[nt][3] + bb1, 0.f) };
            *(float2*)(g_h + (size_t)p1*128 + 64 + col) = v1;
        }
    }
}

// ---------------- kernel B: out = [conv0_1(h0) | relu(conv1_1(h1)) @ W12 + b12] + x ------
__global__ __launch_bounds__(NTHR, 1)
void convB(const int* __restrict__ nbr,
           const float* __restrict__ b01, const float* __restrict__ b11,
           const float* __restrict__ b12, const float* __restrict__ x,
           float* __restrict__ out) {
    extern __shared__ unsigned sm[];
    unsigned* As = sm;                    // MT x ASTR
    unsigned* Ws = As + MT * ASTR;        // 8192 words (packed [64,128] cat slice)
    int*      nb = (int*)(Ws + 8192);

    const int base = blockIdx.x * MT;
    const int tid  = threadIdx.x;
    const int rows = min(MT, NPTS - base);

    for (int i = tid; i < rows * K3; i += NTHR) nb[i] = nbr[(size_t)base * K3 + i];

    float acc0[8][4] = {};   // out0 pre-bias
    float acc1[8][4] = {};   // conv1_1 pre-relu
    const int lane = tid & 31, warp = tid >> 5;
    const int row0 = warp * 16;
    const int gr = lane >> 2, gc = lane & 3;
    const int gR = tid >> 1, gH = tid & 1;

    for (int k = 0; k < K3; ++k) {
        __syncthreads();
        {
            int idx = (gR < rows) ? nb[gR * K3 + k] : NPTS;
            unsigned* dst = As + gR * ASTR + gH * 64;
            if (idx < NPTS) {
                const float4* src = (const float4*)(g_h + (size_t)idx * 128 + gH * 64);
                #pragma unroll
                for (int j = 0; j < 16; ++j) {
                    float4 v = src[j];
                    uint4 u = { f2tf(v.x), f2tf(v.y), f2tf(v.z), f2tf(v.w) };
                    *(uint4*)(dst + j * 4) = u;
                }
            } else {
                uint4 z = {0u,0u,0u,0u};
                #pragma unroll
                for (int j = 0; j < 16; ++j) *(uint4*)(dst + j * 4) = z;
            }
        }
        {
            const unsigned* Wg = g_Wcatp + k * (CH * 128);
            #pragma unroll
            for (int i2 = 0; i2 < (CH*128)/(NTHR*4); ++i2) {
                int i = (i2 * NTHR + tid) * 4;
                *(uint4*)(Ws + i) = *(const uint4*)(Wg + i);
            }
        }
        __syncthreads();
        #pragma unroll
        for (int g = 0; g < 8; ++g) {
            const int c = g * 8;
            // half 0: h0 cols (0..63) x W01 -> acc0
            {
                unsigned a0 = As[(row0+gr  ) * ASTR + c + gc];
                unsigned a1 = As[(row0+gr+8) * ASTR + c + gc];
                unsigned a2 = As[(row0+gr  ) * ASTR + c + gc + 4];
                unsigned a3 = As[(row0+gr+8) * ASTR + c + gc + 4];
                #pragma unroll
                for (int nt = 0; nt < 8; ++nt) {
                    uint2 b = *(uint2*)(Ws + g*1024 + (nt*8 + (lane>>2))*8 + (lane&3)*2);
                    mma_tf32(acc0[nt], a0, a1, a2, a3, b.x, b.y);
                }
            }
            // half 1: h1 cols (64..127) x W11 -> acc1
            {
                unsigned a0 = As[(row0+gr  ) * ASTR + 64 + c + gc];
                unsigned a1 = As[(row0+gr+8) * ASTR + 64 + c + gc];
                unsigned a2 = As[(row0+gr  ) * ASTR + 64 + c + gc + 4];
                unsigned a3 = As[(row0+gr+8) * ASTR + 64 + c + gc + 4];
                #pragma unroll
                for (int nt = 0; nt < 8; ++nt) {
                    uint2 b = *(uint2*)(Ws + g*1024 + (64 + nt*8 + (lane>>2))*8 + (lane&3)*2);
                    mma_tf32(acc1[nt], a0, a1, a2, a3, b.x, b.y);
                }
            }
        }
    }

    __syncthreads();   // all reads of As/Ws done
    // ---- stage h1b = relu(acc1 + b11) into As (stride 68, tf32); store out0 ----
    const int rr0 = row0 + gr, rr1 = rr0 + 8;
    const int p0 = base + rr0, p1 = base + rr1;
    #pragma unroll
    for (int nt = 0; nt < 8; ++nt) {
        const int col = nt * 8 + (lane & 3) * 2;
        float bv0 = b11[col], bv1 = b11[col+1];
        As[rr0*68 + col  ] = f2tf(fmaxf(acc1[nt][0] + bv0, 0.f));
        As[rr0*68 + col+1] = f2tf(fmaxf(acc1[nt][1] + bv1, 0.f));
        As[rr1*68 + col  ] = f2tf(fmaxf(acc1[nt][2] + bv0, 0.f));
        As[rr1*68 + col+1] = f2tf(fmaxf(acc1[nt][3] + bv1, 0.f));
        float bo0 = b01[col], bo1 = b01[col+1];
        if (p0 < NPTS) {
            float2 xv = *(const float2*)(x + (size_t)p0*128 + col);
            float2 v = { acc0[nt][0] + bo0 + xv.x, acc0[nt][1] + bo1 + xv.y };
            *(float2*)(out + (size_t)p0*128 + col) = v;
        }
        if (p1 < NPTS) {
            float2 xv = *(const float2*)(x + (size_t)p1*128 + col);
            float2 v = { acc0[nt][2] + bo0 + xv.x, acc0[nt][3] + bo1 + xv.y };
            *(float2*)(out + (size_t)p1*128 + col) = v;
        }
    }
    // W12 packed -> Ws
    #pragma unroll
    for (int i2 = 0; i2 < (CH*CH)/(NTHR*4); ++i2) {
        int i = (i2 * NTHR + tid) * 4;
        *(uint4*)(Ws + i) = *(const uint4*)(g_W12p + i);
    }
    __syncthreads();

    // ---- 1x1 epilogue GEMM: acc2 = h1b @ W12 ----
    float acc2[8][4] = {};
    #pragma unroll
    for (int g = 0; g < 8; ++g) {
        const int c = g * 8;
        unsigned a0 = As[(row0+gr  ) * 68 + c + gc];
        unsigned a1 = As[(row0+gr+8) * 68 + c + gc];
        unsigned a2 = As[(row0+gr  ) * 68 + c + gc + 4];
        unsigned a3 = As[(row0+gr+8) * 68 + c + gc + 4];
        #pragma unroll
        for (int nt = 0; nt < 8; ++nt) {
            uint2 b = *(uint2*)(Ws + g*(CH*8) + (nt*8 + (lane>>2))*8 + (lane&3)*2);
            mma_tf32(acc2[nt], a0, a1, a2, a3, b.x, b.y);
        }
    }
    #pragma unroll
    for (int nt = 0; nt < 8; ++nt) {
        const int col = nt * 8 + (lane & 3) * 2;
        float bv0 = b12[col], bv1 = b12[col+1];
        if (p0 < NPTS) {
            float2 xv = *(const float2*)(x + (size_t)p0*128 + 64 + col);
            float2 v = { acc2[nt][0] + bv0 + xv.x, acc2[nt][1] + bv1 + xv.y };
            *(float2*)(out + (size_t)p0*128 + 64 + col) = v;
        }
        if (p1 < NPTS) {
            float2 xv = *(const float2*)(x + (size_t)p1*128 + 64 + col);
            float2 v = { acc2[nt][2] + bv0 + xv.x, acc2[nt][3] + bv1 + xv.y };
            *(float2*)(out + (size_t)p1*128 + 64 + col) = v;
        }
    }
}

// ---------------- launch ----------------
extern "C" void kernel_launch(void* const* d_in, const int* in_sizes, int n_in,
                              void* d_out, int out_size) {
    const float* x   = (const float*)d_in[0];
    const int*   nbr = (const int*)  d_in[1];
    const float* W00 = (const float*)d_in[2];
    const float* b00 = (const float*)d_in[3];
    const float* W01 = (const float*)d_in[4];
    const float* b01 = (const float*)d_in[5];
    const float* W10 = (const float*)d_in[6];
    const float* b10 = (const float*)d_in[7];
    const float* W11 = (const float*)d_in[8];
    const float* b11 = (const float*)d_in[9];
    const float* W12 = (const float*)d_in[10];
    const float* b12 = (const float*)d_in[11];
    float* out = (float*)d_out;

    cudaFuncSetAttribute(convA, cudaFuncAttributeMaxDynamicSharedMemorySize, SMEM_BYTES);
    cudaFuncSetAttribute(convB, cudaFuncAttributeMaxDynamicSharedMemorySize, SMEM_BYTES);

    pack_weights<<<(PACK_TOTAL + 255) / 256, 256>>>(W00, W01, W11, W10, W12);

    const int grid = (NPTS + MT - 1) / MT;   // 391
    convA<<<grid, NTHR, SMEM_BYTES>>>(x, nbr, b00, b10);
    convB<<<grid, NTHR, SMEM_BYTES>>>(nbr, b01, b11, b12, x, out);
}